// round 4
// baseline (speedup 1.0000x reference)
#include <cuda_runtime.h>
#include <cuda_bf16.h>

// Skinning: out[b,v,i] = sum_j w[v,j] * (M[b,j,i,:] . [x,y,z,1])
// vertices:  [1, V, 3]    float32 (d_in[0])
// weights:   [1, V, J]    float32 (d_in[1]), J = 52
// M:         [B, J, 4, 4] float32 (d_in[2])
// out:       [B, V, 3]    float32
//
// R4: f32x2 packing over VERTEX pairs (not batch pairs):
//  - weight f32x2 operands fall directly out of one coalesced LDG.128 (no MOVs)
//  - matrix operands pre-splatted (m,m) in smem at fill time -> 6 broadcast
//    LDS.128 per (b,j), zero per-iteration packing ALU
//  - launch_bounds(128,5) to raise occupancy (R3 was capped at 25%)

#define J_JOINTS 52
#define TPB      128
#define BCHUNK   8            // batches per block
#define VPT      4            // vertices per thread (2 f32x2 pairs)
#define MAXV     100000

typedef unsigned long long u64;

// Transposed weights scratch: wT[j*V + v]
__device__ float g_wT[J_JOINTS * MAXV];

__device__ __forceinline__ u64 pack2(float a, float b) {
    u64 r;
    asm("mov.b64 %0, {%1, %2};" : "=l"(r) : "f"(a), "f"(b));
    return r;
}
__device__ __forceinline__ void unpack2(u64 v, float& a, float& b) {
    asm("mov.b64 {%0, %1}, %2;" : "=f"(a), "=f"(b) : "l"(v));
}
__device__ __forceinline__ u64 ffma2(u64 a, u64 b, u64 c) {
    u64 d;
    asm("fma.rn.f32x2 %0, %1, %2, %3;" : "=l"(d) : "l"(a), "l"(b), "l"(c));
    return d;
}

// ---------------- weight transpose: W[v][j] -> wT[j][v] ----------------
#define TR_VERTS 64
__global__ void transpose_w_kernel(const float* __restrict__ w, int V)
{
    __shared__ float sm[TR_VERTS * 53];   // padded stride 53
    const int v0 = blockIdx.x * TR_VERTS;
    const int nv = min(TR_VERTS, V - v0);
    const int total = nv * J_JOINTS;

    for (int idx = threadIdx.x; idx < total; idx += blockDim.x) {
        int i = idx / J_JOINTS;
        int j = idx - i * J_JOINTS;
        sm[i * 53 + j] = w[(size_t)(v0 + i) * J_JOINTS + j];
    }
    __syncthreads();

    for (int idx = threadIdx.x; idx < J_JOINTS * nv; idx += blockDim.x) {
        int j = idx / nv;
        int i = idx - j * nv;
        g_wT[(size_t)j * V + v0 + i] = sm[i * 53 + j];
    }
}

// ---------------- main skinning kernel ----------------
__global__ __launch_bounds__(TPB, 5)
void skinning_kernel(const float* __restrict__ verts,
                     const float* __restrict__ xf,
                     float* __restrict__ out,
                     int V, int B)
{
    // sM[b][j][q], q=0..5: rows 0..2 of M[b,j], each value splatted (m,m).
    // q=0: (M0x,M0x),(M0y,M0y)  q=1: (M0z,M0z),(M0w,M0w)  etc.
    __shared__ double2 sM[BCHUNK][J_JOINTS][6];     // 8*52*96B = 39.9 KB

    const int b0 = blockIdx.y * BCHUNK;

    // Cooperative fill: one (b, j, row) -> 2 double2 of splatted pairs.
    const int nElems = BCHUNK * J_JOINTS * 3;       // 1248
    for (int i = threadIdx.x; i < nElems; i += TPB) {
        int bb  = i / (J_JOINTS * 3);
        int rem = i - bb * (J_JOINTS * 3);
        int j   = rem / 3;
        int r   = rem - j * 3;
        int b   = b0 + bb;
        float4 m = make_float4(0.f, 0.f, 0.f, 0.f);
        if (b < B)
            m = *reinterpret_cast<const float4*>(
                &xf[((size_t)b * J_JOINTS + j) * 16 + r * 4]);
        double2 dA, dB;
        dA.x = __longlong_as_double((long long)pack2(m.x, m.x));
        dA.y = __longlong_as_double((long long)pack2(m.y, m.y));
        dB.x = __longlong_as_double((long long)pack2(m.z, m.z));
        dB.y = __longlong_as_double((long long)pack2(m.w, m.w));
        sM[bb][j][r * 2 + 0] = dA;
        sM[bb][j][r * 2 + 1] = dB;
    }
    __syncthreads();

    const int t  = blockIdx.x * TPB + threadIdx.x;
    const int v0 = t * VPT;
    if (v0 >= V) return;

    // Vertex coords packed as (v, v+1) pairs. V is a multiple of 4 here, but
    // clamp defensively.
    u64 X[2], Y[2], Z[2];
#pragma unroll
    for (int p = 0; p < 2; p++) {
        int va = min(v0 + 2 * p,     V - 1);
        int vb = min(v0 + 2 * p + 1, V - 1);
        X[p] = pack2(verts[va * 3 + 0], verts[vb * 3 + 0]);
        Y[p] = pack2(verts[va * 3 + 1], verts[vb * 3 + 1]);
        Z[p] = pack2(verts[va * 3 + 2], verts[vb * 3 + 2]);
    }

#pragma unroll 1
    for (int bb = 0; bb < BCHUNK; bb++) {
        const int b = b0 + bb;
        if (b >= B) break;

        u64 A0[2], A1[2], A2[2];
#pragma unroll
        for (int p = 0; p < 2; p++) { A0[p] = 0ULL; A1[p] = 0ULL; A2[p] = 0ULL; }

#pragma unroll 4
        for (int j = 0; j < J_JOINTS; j++) {
            // 6 broadcast LDS.128: all 12 splatted M operands.
            double2 e0 = sM[bb][j][0];
            double2 e1 = sM[bb][j][1];
            double2 e2 = sM[bb][j][2];
            double2 e3 = sM[bb][j][3];
            double2 e4 = sM[bb][j][4];
            double2 e5 = sM[bb][j][5];
            u64 M0x = (u64)__double_as_longlong(e0.x);
            u64 M0y = (u64)__double_as_longlong(e0.y);
            u64 M0z = (u64)__double_as_longlong(e1.x);
            u64 M0w = (u64)__double_as_longlong(e1.y);
            u64 M1x = (u64)__double_as_longlong(e2.x);
            u64 M1y = (u64)__double_as_longlong(e2.y);
            u64 M1z = (u64)__double_as_longlong(e3.x);
            u64 M1w = (u64)__double_as_longlong(e3.y);
            u64 M2x = (u64)__double_as_longlong(e4.x);
            u64 M2y = (u64)__double_as_longlong(e4.y);
            u64 M2z = (u64)__double_as_longlong(e5.x);
            u64 M2w = (u64)__double_as_longlong(e5.y);

            // Weights for 4 consecutive vertices: one LDG.128 = two u64 operands.
            double2 wd = *reinterpret_cast<const double2*>(&g_wT[(size_t)j * V + v0]);
            u64 W[2];
            W[0] = (u64)__double_as_longlong(wd.x);   // (w[v0],   w[v0+1])
            W[1] = (u64)__double_as_longlong(wd.y);   // (w[v0+2], w[v0+3])

#pragma unroll
            for (int p = 0; p < 2; p++) {
                u64 r0 = ffma2(M0x, X[p], ffma2(M0y, Y[p], ffma2(M0z, Z[p], M0w)));
                u64 r1 = ffma2(M1x, X[p], ffma2(M1y, Y[p], ffma2(M1z, Z[p], M1w)));
                u64 r2 = ffma2(M2x, X[p], ffma2(M2y, Y[p], ffma2(M2z, Z[p], M2w)));
                A0[p] = ffma2(W[p], r0, A0[p]);
                A1[p] = ffma2(W[p], r1, A1[p]);
                A2[p] = ffma2(W[p], r2, A2[p]);
            }
        }

        // Unpack: pair p -> vertices v0+2p (lo), v0+2p+1 (hi).
        float o00, o01, o02, o10, o11, o12, o20, o21, o22, o30, o31, o32;
        unpack2(A0[0], o00, o10);
        unpack2(A1[0], o01, o11);
        unpack2(A2[0], o02, o12);
        unpack2(A0[1], o20, o30);
        unpack2(A1[1], o21, o31);
        unpack2(A2[1], o22, o32);

        const int nv = min(VPT, V - v0);
        float* o = out + ((size_t)b * V + v0) * 3;
        if (nv == VPT) {
            float4* o4 = reinterpret_cast<float4*>(o);
            o4[0] = make_float4(o00, o01, o02, o10);
            o4[1] = make_float4(o11, o12, o20, o21);
            o4[2] = make_float4(o22, o30, o31, o32);
        } else {
            float vals[12] = {o00,o01,o02, o10,o11,o12, o20,o21,o22, o30,o31,o32};
            for (int k = 0; k < nv * 3; k++) o[k] = vals[k];
        }
    }
}

extern "C" void kernel_launch(void* const* d_in, const int* in_sizes, int n_in,
                              void* d_out, int out_size)
{
    const float* verts   = (const float*)d_in[0];
    const float* weights = (const float*)d_in[1];
    const float* xf      = (const float*)d_in[2];
    float*       out     = (float*)d_out;

    const int V = in_sizes[0] / 3;
    const int B = in_sizes[2] / (J_JOINTS * 16);

    {
        dim3 grid((V + TR_VERTS - 1) / TR_VERTS);
        transpose_w_kernel<<<grid, 256>>>(weights, V);
    }
    {
        const int threads = (V + VPT - 1) / VPT;
        dim3 grid((threads + TPB - 1) / TPB, (B + BCHUNK - 1) / BCHUNK);
        skinning_kernel<<<grid, TPB>>>(verts, xf, out, V, B);
    }
}

// round 7
// speedup vs baseline: 1.0504x; 1.0504x over previous
#include <cuda_runtime.h>
#include <cuda_bf16.h>
#include <mma.h>
#include <cstdint>

using namespace nvcuda;

// Skinning as split-precision bf16 GEMM via wmma (legacy HMMA, works on sm_100):
//   out[b,v,i] = sum_{j,c} F[v,4j+c] * H[4j+c,3b+i]
//   F[v,k] = w[v,j]*vh[v,c], vh=(x,y,z,1);  H[k,n] = M[b,j,i,c], n=3b+i
// GEMM M=100000 (128/CTA), N=96, K=208 (13 x k16)
// bf16 2-split: hi = truncate(f) [exact], lo = bf16_rn(f-hi)
// passes: Ahi*Bhi + Ahi*Blo + Alo*Bhi  (Alo*Blo ~2^-16, dropped)

#define JJ     52
#define KDIM   208
#define NDIM   96
#define TPB    256
#define MTILE  128          // vertices per CTA

// padded strides (conflict-avoidance + wmma ldm rules)
#define A_LD   216          // elems, mult of 8
#define B_LD   104          // elems, mult of 8
#define D_LD   100          // f32 elems, mult of 4

// smem layout (bytes)
#define OFF_AHI 0
#define SZ_A    (MTILE * A_LD * 2)            // 55296
#define OFF_ALO (OFF_AHI + SZ_A)
#define OFF_BHI (OFF_ALO + SZ_A)              // 110592
#define SZ_B    (KDIM * B_LD * 2)             // 43264
#define OFF_BLO (OFF_BHI + SZ_B)
#define SMEM_TOTAL (OFF_BLO + SZ_B)           // 197120

// B-operand gmem images (built by pre-kernel)
__device__ __nv_bfloat16 g_Hhi[KDIM * B_LD];
__device__ __nv_bfloat16 g_Hlo[KDIM * B_LD];

__device__ __forceinline__ void split_bf16(float f, unsigned short& hi, unsigned short& lo)
{
    uint32_t fb = __float_as_uint(f);
    uint32_t hb = fb & 0xffff0000u;
    hi = (unsigned short)(hb >> 16);
    float res = f - __uint_as_float(hb);
    __nv_bfloat16 lb = __float2bfloat16_rn(res);
    lo = *reinterpret_cast<unsigned short*>(&lb);
}

// ---------------- pre-kernel: H images ----------------
__global__ void hbuild_kernel(const float* __restrict__ xf)
{
    int idx = blockIdx.x * blockDim.x + threadIdx.x;
    if (idx >= KDIM * NDIM) return;
    int k = idx / NDIM;
    int n = idx - k * NDIM;
    int j = k >> 2, c = k & 3;
    int b = n / 3, i = n - 3 * b;

    float f = xf[(((size_t)b * JJ + j) << 4) + (i << 2) + c];
    unsigned short hi, lo;
    split_bf16(f, hi, lo);
    g_Hhi[k * B_LD + n] = *reinterpret_cast<__nv_bfloat16*>(&hi);
    g_Hlo[k * B_LD + n] = *reinterpret_cast<__nv_bfloat16*>(&lo);
}

// ---------------- main kernel ----------------
__global__ __launch_bounds__(TPB)
void skin_wmma_kernel(const float* __restrict__ verts,
                      const float* __restrict__ w,
                      float* __restrict__ out,
                      int V)
{
    extern __shared__ __align__(16) unsigned char smem[];
    __nv_bfloat16* sAhi = reinterpret_cast<__nv_bfloat16*>(smem + OFF_AHI);
    __nv_bfloat16* sAlo = reinterpret_cast<__nv_bfloat16*>(smem + OFF_ALO);
    __nv_bfloat16* sBhi = reinterpret_cast<__nv_bfloat16*>(smem + OFF_BHI);
    __nv_bfloat16* sBlo = reinterpret_cast<__nv_bfloat16*>(smem + OFF_BLO);
    float*         sD   = reinterpret_cast<float*>(smem + OFF_AHI);   // aliases A (dead post-MMA)

    const int tid  = threadIdx.x;
    const int warp = tid >> 5;
    const int v0   = blockIdx.x * MTILE;

    // ---- copy B images to smem ----
    {
        const float4* s1 = reinterpret_cast<const float4*>(g_Hhi);
        const float4* s2 = reinterpret_cast<const float4*>(g_Hlo);
        float4* d1 = reinterpret_cast<float4*>(sBhi);
        float4* d2 = reinterpret_cast<float4*>(sBlo);
        const int n16 = SZ_B / 16;
        for (int i = tid; i < n16; i += TPB) {
            d1[i] = s1[i];
            d2[i] = s2[i];
        }
    }

    // ---- build A (F hi/lo): 2 threads per vertex row, 26 joints each ----
    {
        const int vl    = tid >> 1;
        const int jbase = (tid & 1) * 26;
        const int vg    = min(v0 + vl, V - 1);
        float vh[4];
        vh[0] = verts[vg * 3 + 0];
        vh[1] = verts[vg * 3 + 1];
        vh[2] = verts[vg * 3 + 2];
        vh[3] = 1.0f;
        const float* wr = w + (size_t)vg * JJ + jbase;
        uint32_t* rowHi = reinterpret_cast<uint32_t*>(sAhi + (size_t)vl * A_LD);
        uint32_t* rowLo = reinterpret_cast<uint32_t*>(sAlo + (size_t)vl * A_LD);
#pragma unroll 2
        for (int q = 0; q < 26; q++) {
            const float wv = wr[q];
            const int k = (jbase + q) * 4;
            unsigned short h[4], l[4];
#pragma unroll
            for (int c = 0; c < 4; c++) {
                split_bf16(wv * vh[c], h[c], l[c]);
            }
            rowHi[(k >> 1) + 0] = (uint32_t)h[0] | ((uint32_t)h[1] << 16);
            rowHi[(k >> 1) + 1] = (uint32_t)h[2] | ((uint32_t)h[3] << 16);
            rowLo[(k >> 1) + 0] = (uint32_t)l[0] | ((uint32_t)l[1] << 16);
            rowLo[(k >> 1) + 1] = (uint32_t)l[2] | ((uint32_t)l[3] << 16);
        }
    }
    __syncthreads();

    // ---- MMA: each warp owns 16 vertex rows x all 6 n-tiles ----
    wmma::fragment<wmma::accumulator, 16, 16, 16, float> acc[6];
#pragma unroll
    for (int n = 0; n < 6; n++) wmma::fill_fragment(acc[n], 0.0f);

    const __nv_bfloat16* aRow = sAhi + (size_t)(warp * 16) * A_LD;   // hi base

#pragma unroll 1
    for (int pass = 0; pass < 3; pass++) {
        const __nv_bfloat16* Ab = (pass == 2) ? (aRow + (SZ_A / 2)) : aRow;   // sAlo offset = SZ_A/2 elems
        const __nv_bfloat16* Bb = (pass == 1) ? sBlo : sBhi;
#pragma unroll 1
        for (int k = 0; k < 13; k++) {
            wmma::fragment<wmma::matrix_a, 16, 16, 16, __nv_bfloat16, wmma::row_major> af;
            wmma::load_matrix_sync(af, Ab + k * 16, A_LD);
#pragma unroll
            for (int n = 0; n < 6; n++) {
                wmma::fragment<wmma::matrix_b, 16, 16, 16, __nv_bfloat16, wmma::row_major> bf;
                wmma::load_matrix_sync(bf, Bb + (size_t)(k * 16) * B_LD + n * 16, B_LD);
                wmma::mma_sync(acc[n], af, bf, acc[n]);
            }
        }
    }

    __syncthreads();   // A region dead; safe to overwrite with sD

    // ---- stage D in smem: sD[128][D_LD] ----
#pragma unroll
    for (int n = 0; n < 6; n++) {
        wmma::store_matrix_sync(sD + (size_t)(warp * 16) * D_LD + n * 16, acc[n],
                                D_LD, wmma::mem_row_major);
    }
    __syncthreads();

    // ---- coalesced output: per batch b, 128 vertices * 3 floats contiguous ----
    const size_t V3 = (size_t)V * 3;
    const int nValid = min(MTILE, V - v0);          // valid vertices in this CTA
    const int lim = nValid * 3;
#pragma unroll 1
    for (int b = 0; b < 32; b++) {
        float* ob = out + (size_t)b * V3 + (size_t)v0 * 3;
        for (int idx = tid; idx < lim; idx += TPB) {
            const int vv = idx / 3;
            const int i  = idx - vv * 3;
            ob[idx] = sD[(size_t)vv * D_LD + 3 * b + i];
        }
    }
}

// ---------------- launch ----------------
extern "C" void kernel_launch(void* const* d_in, const int* in_sizes, int n_in,
                              void* d_out, int out_size)
{
    const float* verts   = (const float*)d_in[0];
    const float* weights = (const float*)d_in[1];
    const float* xf      = (const float*)d_in[2];
    float*       out     = (float*)d_out;

    const int V = in_sizes[0] / 3;

    {
        const int total = KDIM * NDIM;
        hbuild_kernel<<<(total + 255) / 256, 256>>>(xf);
    }
    {
        cudaFuncSetAttribute(skin_wmma_kernel,
                             cudaFuncAttributeMaxDynamicSharedMemorySize, SMEM_TOTAL);
        const int grid = (V + MTILE - 1) / MTILE;
        skin_wmma_kernel<<<grid, TPB, SMEM_TOTAL>>>(verts, weights, out, V);
    }
}

// round 8
// speedup vs baseline: 2.2283x; 2.1214x over previous
#include <cuda_runtime.h>
#include <cuda_bf16.h>
#include <cstdint>

// Skinning as split-precision bf16 GEMM via raw mma.sync.m16n8k16 (sm_80+ path,
// accepted by plain compute_100 ptxas):
//   out[b,v,i] = sum_{j,c} F[v,4j+c] * H[4j+c,3b+i]
//   F[v,k] = w[v,j]*vh[v,c], vh=(x,y,z,1);  H[k,n] = M[b,j,i,c], n=3b+i
// GEMM M=100000 (128/CTA), N=96 (12 n8-tiles), K=208 (13 k16-tiles)
// bf16 2-split: hi = truncate(f) [exact], lo = bf16_rn(f-hi)
// passes per (k,n): Ahi*Bhi + Ahi*Blo + Alo*Bhi
//
// R8 vs R7: A fragments built DIRECTLY in registers (no A smem, no A LDSM),
// B staged n-major so fragments are two 32-bit LDS, smem 197KB -> 109KB
// (2 CTAs/SM), B frags reused across the 3 passes.

#define JJ    52
#define KDIM  208
#define NDIM  96
#define TPB   256
#define MTILE 128
#define KLD   216            // bf16 elems per BT row (208 + 8 pad)
#define DLD   100            // f32 elems per sD row

// smem layout (bytes)
#define OFF_BTHI 0
#define SZ_BT    (NDIM * KLD * 2)            // 41472
#define OFF_BTLO (OFF_BTHI + SZ_BT)
#define OFF_W    (OFF_BTLO + SZ_BT)          // 82944
#define SZ_W     (MTILE * JJ * 4)            // 26624
#define OFF_V    (OFF_W + SZ_W)              // 109568
#define SZ_V     (MTILE * 4 * 4)             // 2048
#define SMEM_TOTAL (OFF_V + SZ_V)            // 111616 (~109 KB)

// B-operand gmem images, n-major: g_BT*[n*KLD + k]
__device__ __nv_bfloat16 g_BThi[NDIM * KLD];
__device__ __nv_bfloat16 g_BTlo[NDIM * KLD];

__device__ __forceinline__ void split_bf16(float f, unsigned short& hi, unsigned short& lo)
{
    uint32_t fb = __float_as_uint(f);
    uint32_t hb = fb & 0xffff0000u;
    hi = (unsigned short)(hb >> 16);
    float res = f - __uint_as_float(hb);
    __nv_bfloat16 lb = __float2bfloat16_rn(res);
    lo = *reinterpret_cast<unsigned short*>(&lb);
}

// pack hi: low16 = top bits of f0, high16 = top bits of f1
__device__ __forceinline__ uint32_t pack_hi(float f0, float f1)
{
    uint32_t r;
    asm("prmt.b32 %0, %1, %2, 0x7632;"
        : "=r"(r) : "r"(__float_as_uint(f0)), "r"(__float_as_uint(f1)));
    return r;
}
// pack lo residuals: low16 = bf16(l0), high16 = bf16(l1)
__device__ __forceinline__ uint32_t pack_lo(float f0, float f1)
{
    float l0 = f0 - __uint_as_float(__float_as_uint(f0) & 0xffff0000u);
    float l1 = f1 - __uint_as_float(__float_as_uint(f1) & 0xffff0000u);
    uint32_t r;
    asm("cvt.rn.bf16x2.f32 %0, %1, %2;" : "=r"(r) : "f"(l1), "f"(l0));
    return r;
}

__device__ __forceinline__ void mma16816(float* c, const uint32_t* a, uint32_t b0, uint32_t b1)
{
    asm volatile(
        "mma.sync.aligned.m16n8k16.row.col.f32.bf16.bf16.f32 "
        "{%0,%1,%2,%3}, {%4,%5,%6,%7}, {%8,%9}, {%0,%1,%2,%3};"
        : "+f"(c[0]), "+f"(c[1]), "+f"(c[2]), "+f"(c[3])
        : "r"(a[0]), "r"(a[1]), "r"(a[2]), "r"(a[3]), "r"(b0), "r"(b1));
}

// ---------------- pre-kernel: transposed H images ----------------
__global__ void hbuild_kernel(const float* __restrict__ xf)
{
    int idx = blockIdx.x * blockDim.x + threadIdx.x;
    if (idx >= KDIM * NDIM) return;
    int k = idx / NDIM;
    int n = idx - k * NDIM;
    int j = k >> 2, c = k & 3;
    int b = n / 3, i = n - 3 * b;

    float f = xf[(((size_t)b * JJ + j) << 4) + (i << 2) + c];
    unsigned short hi, lo;
    split_bf16(f, hi, lo);
    g_BThi[n * KLD + k] = *reinterpret_cast<__nv_bfloat16*>(&hi);
    g_BTlo[n * KLD + k] = *reinterpret_cast<__nv_bfloat16*>(&lo);
}

// ---------------- main kernel ----------------
__global__ __launch_bounds__(TPB, 2)
void skin_mma_kernel(const float* __restrict__ verts,
                     const float* __restrict__ w,
                     float* __restrict__ out,
                     int V)
{
    extern __shared__ __align__(16) unsigned char smem[];
    float* sW = reinterpret_cast<float*>(smem + OFF_W);   // [128][52]
    float* sV = reinterpret_cast<float*>(smem + OFF_V);   // [128][4], vh
    float* sD = reinterpret_cast<float*>(smem);           // aliases BT post-MMA

    const int tid  = threadIdx.x;
    const int v0   = blockIdx.x * MTILE;

    // ---- stage B images (hi+lo back-to-back = one linear copy) ----
    {
        const float4* s1 = reinterpret_cast<const float4*>(g_BThi);
        const float4* s2 = reinterpret_cast<const float4*>(g_BTlo);
        float4* d1 = reinterpret_cast<float4*>(smem + OFF_BTHI);
        float4* d2 = reinterpret_cast<float4*>(smem + OFF_BTLO);
        const int n16 = SZ_BT / 16;
        for (int i = tid; i < n16; i += TPB) {
            d1[i] = s1[i];
            d2[i] = s2[i];
        }
    }
    // ---- stage weights (row-clamped) ----
    for (int i = tid; i < MTILE * JJ; i += TPB) {
        int r  = i / JJ;
        int j  = i - r * JJ;
        int vv = min(v0 + r, V - 1);
        sW[i] = w[(size_t)vv * JJ + j];
    }
    // ---- stage homogeneous vertex coords ----
    for (int i = tid; i < MTILE; i += TPB) {
        int vv = min(v0 + i, V - 1);
        sV[i * 4 + 0] = verts[vv * 3 + 0];
        sV[i * 4 + 1] = verts[vv * 3 + 1];
        sV[i * 4 + 2] = verts[vv * 3 + 2];
        sV[i * 4 + 3] = 1.0f;
    }
    __syncthreads();

    // ---- per-thread fragment geometry ----
    const int warp = tid >> 5;
    const int lane = tid & 31;
    const int gid  = lane >> 2;       // 0..7
    const int tig  = lane & 3;        // 0..3
    const int r0   = warp * 16 + gid;
    const int r1   = r0 + 8;
    const int c0   = (tig & 1) * 2;   // vh component pair (c0, c0+1)
    const int jadd = tig >> 1;        // joint offset within k-tile

    const float p0 = sV[r0 * 4 + c0];
    const float p1 = sV[r0 * 4 + c0 + 1];
    const float s0 = sV[r1 * 4 + c0];
    const float s1 = sV[r1 * 4 + c0 + 1];

    float acc[12][4];
#pragma unroll
    for (int nt = 0; nt < 12; nt++)
#pragma unroll
        for (int q = 0; q < 4; q++) acc[nt][q] = 0.0f;

    const unsigned char* bhBase = smem + OFF_BTHI + (size_t)gid * (KLD * 2) + tig * 4;
    const unsigned char* blBase = smem + OFF_BTLO + (size_t)gid * (KLD * 2) + tig * 4;

#pragma unroll 1
    for (int t = 0; t < 13; t++) {
        // ---- build A fragments (hi & lo) in registers ----
        const int j0 = 4 * t + jadd;
        const float w00 = sW[r0 * JJ + j0];
        const float w01 = sW[r0 * JJ + j0 + 2];
        const float w10 = sW[r1 * JJ + j0];
        const float w11 = sW[r1 * JJ + j0 + 2];

        float f0, f1;
        uint32_t ahi[4], alo[4];
        f0 = w00 * p0; f1 = w00 * p1;  ahi[0] = pack_hi(f0, f1); alo[0] = pack_lo(f0, f1);
        f0 = w10 * s0; f1 = w10 * s1;  ahi[1] = pack_hi(f0, f1); alo[1] = pack_lo(f0, f1);
        f0 = w01 * p0; f1 = w01 * p1;  ahi[2] = pack_hi(f0, f1); alo[2] = pack_lo(f0, f1);
        f0 = w11 * s0; f1 = w11 * s1;  ahi[3] = pack_hi(f0, f1); alo[3] = pack_lo(f0, f1);

        const int kOff = t * 32;      // (t*16)*2 bytes
#pragma unroll
        for (int nt = 0; nt < 12; nt++) {
            const size_t rowOff = (size_t)nt * (8 * KLD * 2) + kOff;
            uint32_t bh0 = *reinterpret_cast<const uint32_t*>(bhBase + rowOff);
            uint32_t bh1 = *reinterpret_cast<const uint32_t*>(bhBase + rowOff + 16);
            uint32_t bl0 = *reinterpret_cast<const uint32_t*>(blBase + rowOff);
            uint32_t bl1 = *reinterpret_cast<const uint32_t*>(blBase + rowOff + 16);
            mma16816(acc[nt], ahi, bh0, bh1);
            mma16816(acc[nt], ahi, bl0, bl1);
            mma16816(acc[nt], alo, bh0, bh1);
        }
    }

    __syncthreads();   // BT region dead -> reuse as sD

    // ---- stage D: sD[128][DLD] ----
#pragma unroll
    for (int nt = 0; nt < 12; nt++) {
        const int col = nt * 8 + tig * 2;
        sD[r0 * DLD + col]     = acc[nt][0];
        sD[r0 * DLD + col + 1] = acc[nt][1];
        sD[r1 * DLD + col]     = acc[nt][2];
        sD[r1 * DLD + col + 1] = acc[nt][3];
    }
    __syncthreads();

    // ---- coalesced output ----
    const size_t V3 = (size_t)V * 3;
    const int nValid = min(MTILE, V - v0);
    const int lim = nValid * 3;
#pragma unroll 1
    for (int b = 0; b < 32; b++) {
        float* ob = out + (size_t)b * V3 + (size_t)v0 * 3;
        for (int idx = tid; idx < lim; idx += TPB) {
            const int vv = idx / 3;
            const int i  = idx - vv * 3;
            ob[idx] = sD[(size_t)vv * DLD + 3 * b + i];
        }
    }
}

// ---------------- launch ----------------
extern "C" void kernel_launch(void* const* d_in, const int* in_sizes, int n_in,
                              void* d_out, int out_size)
{
    const float* verts   = (const float*)d_in[0];
    const float* weights = (const float*)d_in[1];
    const float* xf      = (const float*)d_in[2];
    float*       out     = (float*)d_out;

    const int V = in_sizes[0] / 3;

    {
        const int total = KDIM * NDIM;
        hbuild_kernel<<<(total + 255) / 256, 256>>>(xf);
    }
    {
        cudaFuncSetAttribute(skin_mma_kernel,
                             cudaFuncAttributeMaxDynamicSharedMemorySize, SMEM_TOTAL);
        const int grid = (V + MTILE - 1) / MTILE;
        skin_mma_kernel<<<grid, TPB, SMEM_TOTAL>>>(verts, weights, out, V);
    }
}